// round 16
// baseline (speedup 1.0000x reference)
#include <cuda_runtime.h>
#include <cuda_bf16.h>
#include <cuda_fp16.h>
#include <cstdint>
#include <math.h>

#define NNODES 100000
#define NEDGES 3200000
#define FIN    512
#define FHID   256
#define NCLS   40

// ---------------- device scratch ----------------
__device__ __half g_H0h[(size_t)NNODES * FHID];  // x @ W1           (fp16)
__device__ __half g_Hh [(size_t)NNODES * FHID];  // relu(spmm+b1)    (fp16)
__device__ __half g_Ph [(size_t)NNODES * NCLS];  // g_H @ W2         (fp16)
__device__ int    g_deg[NNODES];
__device__ int    g_rowptr[NNODES + 1];
__device__ int    g_fill[NNODES];
__device__ int    g_bsum[128];
__device__ int    g_boff[128];
__device__ uint2  g_edge[NEDGES];                // {col, val bits}
__device__ int    g_is64;
// W1 packed fp16x2: [FIN/2 kpairs][FHID]
__device__ uint32_t g_W1p[(size_t)(FIN / 2) * FHID];

// ---------------- helpers ----------------
__device__ __forceinline__ void mma_fp16(float* d, const uint32_t* a, const uint32_t* b) {
    asm volatile(
      "mma.sync.aligned.m16n8k16.row.col.f32.f16.f16.f32 "
      "{%0,%1,%2,%3}, {%4,%5,%6,%7}, {%8,%9}, {%0,%1,%2,%3};\n"
      : "+f"(d[0]), "+f"(d[1]), "+f"(d[2]), "+f"(d[3])
      : "r"(a[0]), "r"(a[1]), "r"(a[2]), "r"(a[3]), "r"(b[0]), "r"(b[1]));
}

__device__ __forceinline__ uint32_t pack_h2(float x, float y) {
    __half2 t = __floats2half2_rn(x, y);
    return *reinterpret_cast<uint32_t*>(&t);
}

__device__ __forceinline__ uint32_t smem_u32(const void* p) {
    uint32_t a;
    asm("{ .reg .u64 t; cvta.to.shared.u64 t, %1; cvt.u32.u64 %0, t; }" : "=r"(a) : "l"(p));
    return a;
}

#define CP_ASYNC16(dst, src, nbytes) \
    asm volatile("cp.async.cg.shared.global [%0], [%1], 16, %2;" \
                 :: "r"(dst), "l"(src), "r"(nbytes))
#define CP_COMMIT() asm volatile("cp.async.commit_group;")
#define CP_WAIT2()  asm volatile("cp.async.wait_group 2;")

// ---------------- edge index width detection (parallel) -----------------
__global__ void detect_kernel(const void* rowp) {
    const int* p = (const int*)rowp;
    int t = threadIdx.x;                       // 128 threads
    int nz = (p[2 * t + 1] != 0) ? 1 : 0;
    unsigned any = __ballot_sync(0xFFFFFFFFu, nz);
    __shared__ int sh[4];
    if ((t & 31) == 0) sh[t >> 5] = (any != 0);
    __syncthreads();
    if (t == 0)
        g_is64 = !(sh[0] | sh[1] | sh[2] | sh[3]);
}

__device__ __forceinline__ int load_idx(const void* p, int i, int is64) {
    return is64 ? (int)((const long long*)p)[i] : ((const int*)p)[i];
}

// ---------------- W1 fp16 packed pre-convert ----------------------------
__global__ __launch_bounds__(256) void w1cvt_kernel(const float* __restrict__ W1) {
    int i = blockIdx.x * 256 + threadIdx.x;
    if (i >= (FIN / 2) * FHID) return;
    int kp = i / FHID, n = i % FHID;
    float v0 = W1[(size_t)(2 * kp) * FHID + n];
    float v1 = W1[(size_t)(2 * kp + 1) * FHID + n];
    g_W1p[i] = pack_h2(v0, v1);
}

// ---------------- CSR build ----------------
__global__ void zero_deg_kernel() {
    int i = blockIdx.x * 1024 + threadIdx.x;
    if (i < NNODES) g_deg[i] = 0;
}

__global__ __launch_bounds__(256) void hist_kernel(const void* rowp) {
    int i = blockIdx.x * 256 + threadIdx.x;
    if (i >= NEDGES) return;
    int r = load_idx(rowp, i, g_is64);
    atomicAdd(&g_deg[r], 1);
}

__global__ __launch_bounds__(1024) void scan_k1_kernel() {
    __shared__ int sh[1024];
    int t = threadIdx.x;
    int i = blockIdx.x * 1024 + t;
    sh[t] = (i < NNODES) ? g_deg[i] : 0;
    __syncthreads();
    for (int off = 512; off > 0; off >>= 1) {
        if (t < off) sh[t] += sh[t + off];
        __syncthreads();
    }
    if (t == 0) g_bsum[blockIdx.x] = sh[0];
}

__global__ void scan_k2_kernel(int nblocks) {
    __shared__ int sh[128];
    int t = threadIdx.x;
    int x = (t < nblocks) ? g_bsum[t] : 0;
    sh[t] = x;
    __syncthreads();
    for (int off = 1; off < 128; off <<= 1) {
        int v = (t >= off) ? sh[t - off] : 0;
        __syncthreads();
        sh[t] += v;
        __syncthreads();
    }
    if (t < nblocks) g_boff[t] = sh[t] - x;
    if (t == 0) g_rowptr[NNODES] = NEDGES;
}

__global__ __launch_bounds__(1024) void scan_k3_kernel() {
    __shared__ int sh[1024];
    int t = threadIdx.x;
    int i = blockIdx.x * 1024 + t;
    int x = (i < NNODES) ? g_deg[i] : 0;
    sh[t] = x;
    __syncthreads();
    for (int off = 1; off < 1024; off <<= 1) {
        int v = (t >= off) ? sh[t - off] : 0;
        __syncthreads();
        sh[t] += v;
        __syncthreads();
    }
    if (i < NNODES) {
        int excl = sh[t] - x + g_boff[blockIdx.x];
        g_rowptr[i] = excl;
        g_fill[i]   = excl;
    }
}

__global__ __launch_bounds__(256) void scatter_kernel(const void* rowp, const void* colp,
                                                      const float* __restrict__ val) {
    int i = blockIdx.x * 256 + threadIdx.x;
    if (i >= NEDGES) return;
    int is64 = g_is64;
    int r = load_idx(rowp, i, is64);
    int c = load_idx(colp, i, is64);
    int pos = atomicAdd(&g_fill[r], 1);
    g_edge[pos] = make_uint2((uint32_t)c, __float_as_uint(val[i]));
}

// ---------------- GEMM1 (fp16 m16n8k16, 4-stage cp.async pipeline) ------
// 256 threads, 8 warps (4m x 2n), 128x128 block, BK=16.
// Every iteration commits exactly one group (empty at the drain), so
// wait_group 2 always guarantees tile `it` has fully landed.
#define STAGES  4
#define ASTF    20                       // fp32 A stride (proven conflict-free)
#define BSTRIDE 136
#define A_STG   (128 * ASTF)             // floats per stage
#define B_STG   (8 * BSTRIDE)            // uint32 per stage
#define G1_SMEM_BYTES ((STAGES * A_STG + STAGES * B_STG) * 4)   // 58368

__global__ __launch_bounds__(256) void gemm1_fp16_kernel(const float* __restrict__ A) {
    extern __shared__ uint32_t usm[];
    float*    As = (float*)usm;                    // [STAGES][A_STG]
    uint32_t* Bs = usm + STAGES * A_STG;           // [STAGES][B_STG]

    const int tid  = threadIdx.x;
    const int lane = tid & 31;
    const int wid  = tid >> 5;
    const int wm   = wid & 3;
    const int wn   = wid >> 2;
    const int bm   = blockIdx.y * 128;
    const int bn   = blockIdx.x * 128;

    const int g  = lane >> 2;
    const int tg = lane & 3;

    const uint32_t sA = smem_u32(As);
    const uint32_t sB = smem_u32(Bs);

    const int aRow0 = tid >> 2;          // 0..63, +64 for second
    const int aC4   = tid & 3;
    const int ldKp  = tid >> 5;          // 0..7
    const int ldN4  = (tid & 31) * 4;    // 0..124

    float acc[2][8][4];
    #pragma unroll
    for (int i = 0; i < 2; i++)
        #pragma unroll
        for (int j = 0; j < 8; j++)
            #pragma unroll
            for (int q = 0; q < 4; q++) acc[i][j][q] = 0.f;

    auto issue_tile = [&](int s, int it) {
        const int k0 = it * 16;
        #pragma unroll
        for (int i = 0; i < 2; i++) {
            int row = aRow0 + i * 64;
            uint32_t dst = sA + (uint32_t)(s * A_STG + row * ASTF + aC4 * 4) * 4;
            const float* src = A + (size_t)(bm + row) * FIN + k0 + aC4 * 4;
            CP_ASYNC16(dst, src, (bm + row < NNODES) ? 16 : 0);
        }
        uint32_t dstB = sB + (uint32_t)(s * B_STG + ldKp * BSTRIDE + ldN4) * 4;
        CP_ASYNC16(dstB, g_W1p + (size_t)(it * 8 + ldKp) * FHID + bn + ldN4, 16);
        CP_COMMIT();
    };

    // prologue: tiles 0..2 (3 groups in flight)
    issue_tile(0, 0);
    issue_tile(1, 1);
    issue_tile(2, 2);

    const int NITER = FIN / 16;   // 32
    for (int it = 0; it < NITER; it++) {
        int s = it & (STAGES - 1);
        CP_WAIT2();               // with uniform commits: tile `it` has landed
        __syncthreads();

        const float*    aS = As + s * A_STG;
        const uint32_t* bS = Bs + s * B_STG;

        // A fragments: LDS fp32 pairs -> pack fp16x2
        uint32_t a[2][4];
        #pragma unroll
        for (int mt = 0; mt < 2; mt++) {
            int r0 = wm * 32 + mt * 16 + g;
            float2 p0 = *(const float2*)&aS[r0 * ASTF + 2 * tg];
            float2 p1 = *(const float2*)&aS[(r0 + 8) * ASTF + 2 * tg];
            float2 p2 = *(const float2*)&aS[r0 * ASTF + 2 * tg + 8];
            float2 p3 = *(const float2*)&aS[(r0 + 8) * ASTF + 2 * tg + 8];
            a[mt][0] = pack_h2(p0.x, p0.y);
            a[mt][1] = pack_h2(p1.x, p1.y);
            a[mt][2] = pack_h2(p2.x, p2.y);
            a[mt][3] = pack_h2(p3.x, p3.y);
        }

        #pragma unroll
        for (int nt = 0; nt < 8; nt++) {
            int n = wn * 64 + nt * 8 + g;
            uint32_t b[2];
            b[0] = bS[tg * BSTRIDE + n];
            b[1] = bS[(tg + 4) * BSTRIDE + n];
            mma_fp16(acc[0][nt], a[0], b);
            mma_fp16(acc[1][nt], a[1], b);
        }

        // uniform commit: real tile or empty group (drain correctness)
        if (it + STAGES - 1 < NITER)
            issue_tile((it + STAGES - 1) & (STAGES - 1), it + STAGES - 1);
        else
            CP_COMMIT();
    }

    // epilogue: write fp16
    #pragma unroll
    for (int mt = 0; mt < 2; mt++) {
        int r0 = bm + wm * 32 + mt * 16 + g;
        #pragma unroll
        for (int nt = 0; nt < 8; nt++) {
            int cc = bn + wn * 64 + nt * 8 + 2 * tg;
            if (r0 < NNODES)
                *(__half2*)(g_H0h + (size_t)r0 * FHID + cc) =
                    __floats2half2_rn(acc[mt][nt][0], acc[mt][nt][1]);
            if (r0 + 8 < NNODES)
                *(__half2*)(g_H0h + (size_t)(r0 + 8) * FHID + cc) =
                    __floats2half2_rn(acc[mt][nt][2], acc[mt][nt][3]);
        }
    }
}

// ---------------- SpMM1 (CSR, warp/row, 4-edge batched fp16 gather) -----
__global__ __launch_bounds__(256) void spmm1_csr_kernel(const float* __restrict__ b1) {
    int row  = blockIdx.x * 8 + (threadIdx.x >> 5);
    int lane = threadIdx.x & 31;
    int start = g_rowptr[row];
    int end   = g_rowptr[row + 1];

    float4 a0 = make_float4(0.f, 0.f, 0.f, 0.f);
    float4 a1 = make_float4(0.f, 0.f, 0.f, 0.f);

    for (int e0 = start; e0 < end; e0 += 32) {
        int m = min(32, end - e0);
        uint2 ev = make_uint2(0u, 0u);
        if (lane < m) ev = g_edge[e0 + lane];
        for (int j = 0; j < m; j += 4) {
            uint2 q0[4], q1[4];
            float vv[4];
            #pragma unroll
            for (int k = 0; k < 4; k++) {
                int   cj = __shfl_sync(0xFFFFFFFFu, (int)ev.x, j + k);
                vv[k] = __uint_as_float(__shfl_sync(0xFFFFFFFFu, ev.y, j + k));
                const uint2* s = (const uint2*)(g_H0h + (size_t)cj * FHID);
                q0[k] = s[lane];
                q1[k] = s[lane + 32];
            }
            #pragma unroll
            for (int k = 0; k < 4; k++) {
                float2 f0 = __half22float2(*(__half2*)&q0[k].x);
                float2 f1 = __half22float2(*(__half2*)&q0[k].y);
                float2 f2 = __half22float2(*(__half2*)&q1[k].x);
                float2 f3 = __half22float2(*(__half2*)&q1[k].y);
                a0.x = fmaf(vv[k], f0.x, a0.x); a0.y = fmaf(vv[k], f0.y, a0.y);
                a0.z = fmaf(vv[k], f1.x, a0.z); a0.w = fmaf(vv[k], f1.y, a0.w);
                a1.x = fmaf(vv[k], f2.x, a1.x); a1.y = fmaf(vv[k], f2.y, a1.y);
                a1.z = fmaf(vv[k], f3.x, a1.z); a1.w = fmaf(vv[k], f3.y, a1.w);
            }
        }
    }

    const float4* bb = (const float4*)b1;
    float4 t0 = bb[lane], t1 = bb[lane + 32];
    a0.x = fmaxf(a0.x + t0.x, 0.f); a0.y = fmaxf(a0.y + t0.y, 0.f);
    a0.z = fmaxf(a0.z + t0.z, 0.f); a0.w = fmaxf(a0.w + t0.w, 0.f);
    a1.x = fmaxf(a1.x + t1.x, 0.f); a1.y = fmaxf(a1.y + t1.y, 0.f);
    a1.z = fmaxf(a1.z + t1.z, 0.f); a1.w = fmaxf(a1.w + t1.w, 0.f);

    uint2* d = (uint2*)(g_Hh + (size_t)row * FHID);
    uint2 o0, o1;
    *(__half2*)&o0.x = __floats2half2_rn(a0.x, a0.y);
    *(__half2*)&o0.y = __floats2half2_rn(a0.z, a0.w);
    *(__half2*)&o1.x = __floats2half2_rn(a1.x, a1.y);
    *(__half2*)&o1.y = __floats2half2_rn(a1.z, a1.w);
    d[lane]      = o0;
    d[lane + 32] = o1;
}

// ---------------- GEMM2: g_Ph = g_Hh @ W2, smem-staged ------------------
#define HTS 260
#define G2_H_SZ   (64 * HTS)
#define G2_W_SZ   (NCLS * HTS)
#define G2_SMEM_BYTES ((G2_H_SZ + G2_W_SZ) * 4)   // 108160

__global__ __launch_bounds__(256) void gemm2_kernel(const float* __restrict__ W2) {
    extern __shared__ float fsm[];
    float* hT   = fsm;
    float* shWT = fsm + G2_H_SZ;

    const int tid = threadIdx.x;
    const int rowbase = blockIdx.x * 64;

    for (int idx = tid; idx < FHID * NCLS; idx += 256) {
        int k = idx / NCLS, c = idx % NCLS;
        shWT[c * HTS + k] = W2[idx];
    }
    #pragma unroll
    for (int i = 0; i < 16; i++) {
        int idx = tid + i * 256;
        int row = idx >> 6, k4 = idx & 63;
        float2 fa = make_float2(0.f, 0.f), fb = make_float2(0.f, 0.f);
        if (rowbase + row < NNODES) {
            uint2 q = *(const uint2*)(g_Hh + (size_t)(rowbase + row) * FHID + k4 * 4);
            fa = __half22float2(*(__half2*)&q.x);
            fb = __half22float2(*(__half2*)&q.y);
        }
        float* p = &hT[row * HTS + k4 * 4];
        p[0] = fa.x; p[1] = fa.y; p[2] = fb.x; p[3] = fb.y;
    }
    __syncthreads();

    const int rp = tid >> 3;
    const int c0 = (tid & 7) * 5;
    const int lr0 = rp * 2, lr1 = lr0 + 1;

    float acc0[5] = {0.f, 0.f, 0.f, 0.f, 0.f};
    float acc1[5] = {0.f, 0.f, 0.f, 0.f, 0.f};

    #pragma unroll 4
    for (int kq = 0; kq < FHID / 4; kq++) {
        float4 ha = *(const float4*)&hT[lr0 * HTS + kq * 4];
        float4 hb = *(const float4*)&hT[lr1 * HTS + kq * 4];
        #pragma unroll
        for (int j = 0; j < 5; j++) {
            float4 w = *(const float4*)&shWT[(c0 + j) * HTS + kq * 4];
            acc0[j] = fmaf(ha.x, w.x, acc0[j]); acc0[j] = fmaf(ha.y, w.y, acc0[j]);
            acc0[j] = fmaf(ha.z, w.z, acc0[j]); acc0[j] = fmaf(ha.w, w.w, acc0[j]);
            acc1[j] = fmaf(hb.x, w.x, acc1[j]); acc1[j] = fmaf(hb.y, w.y, acc1[j]);
            acc1[j] = fmaf(hb.z, w.z, acc1[j]); acc1[j] = fmaf(hb.w, w.w, acc1[j]);
        }
    }

    int r0 = rowbase + lr0, r1 = rowbase + lr1;
    if (r0 < NNODES) {
        __half* p = g_Ph + (size_t)r0 * NCLS + c0;
        #pragma unroll
        for (int j = 0; j < 5; j++) p[j] = __float2half_rn(acc0[j]);
    }
    if (r1 < NNODES) {
        __half* p = g_Ph + (size_t)r1 * NCLS + c0;
        #pragma unroll
        for (int j = 0; j < 5; j++) p[j] = __float2half_rn(acc1[j]);
    }
}

// ---------------- SpMM2 (CSR, warp/row, 8-edge batched gather) ----------
__global__ __launch_bounds__(256) void spmm2_csr_kernel(const float* __restrict__ b2,
                                                        float* __restrict__ out) {
    int row  = blockIdx.x * 8 + (threadIdx.x >> 5);
    int lane = threadIdx.x & 31;
    int start = g_rowptr[row];
    int end   = g_rowptr[row + 1];

    float ax = 0.f, ay = 0.f;
    const bool act = lane < 20;

    for (int e0 = start; e0 < end; e0 += 32) {
        int m = min(32, end - e0);
        uint2 ev = make_uint2(0u, 0u);
        if (lane < m) ev = g_edge[e0 + lane];
        for (int j = 0; j < m; j += 8) {
            uint32_t pv[8];
            float    vv[8];
            #pragma unroll
            for (int k = 0; k < 8; k++) {
                int   cj = __shfl_sync(0xFFFFFFFFu, (int)ev.x, j + k);
                vv[k] = __uint_as_float(__shfl_sync(0xFFFFFFFFu, ev.y, j + k));
                pv[k] = act ? *(const uint32_t*)((const __half2*)(g_Ph + (size_t)cj * NCLS) + lane)
                            : 0u;
            }
            #pragma unroll
            for (int k = 0; k < 8; k++) {
                float2 f = __half22float2(*(__half2*)&pv[k]);
                ax = fmaf(vv[k], f.x, ax);
                ay = fmaf(vv[k], f.y, ay);
            }
        }
    }

    float v0 = act ? (ax + b2[2 * lane])     : -INFINITY;
    float v1 = act ? (ay + b2[2 * lane + 1]) : -INFINITY;

    float mx = fmaxf(v0, v1);
    #pragma unroll
    for (int off = 16; off > 0; off >>= 1)
        mx = fmaxf(mx, __shfl_xor_sync(0xFFFFFFFFu, mx, off));

    float s = act ? (expf(v0 - mx) + expf(v1 - mx)) : 0.f;
    #pragma unroll
    for (int off = 16; off > 0; off >>= 1)
        s += __shfl_xor_sync(0xFFFFFFFFu, s, off);

    float ls = mx + logf(s);
    if (act)
        *(float2*)(out + (size_t)row * NCLS + 2 * lane) =
            make_float2(v0 - ls, v1 - ls);
}

// ---------------- side-stream resources (created once, OUTSIDE capture) --
struct SideRes {
    cudaStream_t s;
    cudaEvent_t  fork;
    cudaEvent_t  join;
};

static SideRes& side_res() {
    static SideRes r = [] {
        SideRes t;
        cudaStreamCreateWithFlags(&t.s, cudaStreamNonBlocking);
        cudaEventCreateWithFlags(&t.fork, cudaEventDisableTiming);
        cudaEventCreateWithFlags(&t.join, cudaEventDisableTiming);
        return t;
    }();
    return r;
}

// ---------------- launch ----------------
extern "C" void kernel_launch(void* const* d_in, const int* in_sizes, int n_in,
                              void* d_out, int out_size) {
    const float* x    = (const float*)d_in[0];
    const void*  erow = d_in[1];
    const void*  ecol = d_in[2];
    const float* eval = (const float*)d_in[3];
    const float* W1   = (const float*)d_in[4];
    const float* b1   = (const float*)d_in[5];
    const float* W2   = (const float*)d_in[6];
    const float* b2   = (const float*)d_in[7];
    float* out = (float*)d_out;

    const int nchunks = (NNODES + 1023) / 1024;
    SideRes& R = side_res();

    detect_kernel<<<1, 128>>>(erow);

    cudaEventRecord(R.fork, 0);
    cudaStreamWaitEvent(R.s, R.fork, 0);

    zero_deg_kernel<<<nchunks, 1024, 0, R.s>>>();
    hist_kernel<<<NEDGES / 256, 256, 0, R.s>>>(erow);
    scan_k1_kernel<<<nchunks, 1024, 0, R.s>>>();
    scan_k2_kernel<<<1, 128, 0, R.s>>>(nchunks);
    scan_k3_kernel<<<nchunks, 1024, 0, R.s>>>();
    scatter_kernel<<<NEDGES / 256, 256, 0, R.s>>>(erow, ecol, eval);
    cudaEventRecord(R.join, R.s);

    w1cvt_kernel<<<((FIN / 2) * FHID + 255) / 256, 256>>>(W1);

    cudaFuncSetAttribute(gemm1_fp16_kernel,
                         cudaFuncAttributeMaxDynamicSharedMemorySize, G1_SMEM_BYTES);
    {
        dim3 grid(FHID / 128, (NNODES + 127) / 128);  // (2, 782)
        gemm1_fp16_kernel<<<grid, 256, G1_SMEM_BYTES>>>(x);
    }

    cudaStreamWaitEvent(0, R.join, 0);

    spmm1_csr_kernel<<<NNODES / 8, 256>>>(b1);

    cudaFuncSetAttribute(gemm2_kernel,
                         cudaFuncAttributeMaxDynamicSharedMemorySize, G2_SMEM_BYTES);
    gemm2_kernel<<<(NNODES + 63) / 64, 256, G2_SMEM_BYTES>>>(W2);

    spmm2_csr_kernel<<<NNODES / 8, 256>>>(b2, out);
}

// round 17
// speedup vs baseline: 1.5084x; 1.5084x over previous
#include <cuda_runtime.h>
#include <cuda_bf16.h>
#include <cuda_fp16.h>
#include <cstdint>
#include <math.h>

#define NNODES 100000
#define NEDGES 3200000
#define FIN    512
#define FHID   256
#define NCLS   40

// ---------------- device scratch ----------------
__device__ __half g_H0h[(size_t)NNODES * FHID];  // x @ W1           (fp16)
__device__ __half g_Hh [(size_t)NNODES * FHID];  // relu(spmm+b1)    (fp16)
__device__ __half g_Ph [(size_t)NNODES * NCLS];  // g_H @ W2         (fp16)
__device__ int    g_deg[NNODES];
__device__ int    g_rowptr[NNODES + 1];
__device__ int    g_fill[NNODES];
__device__ int    g_bsum[128];
__device__ int    g_boff[128];
__device__ uint2  g_edge[NEDGES];                // {col, val bits}
__device__ int    g_is64;
// W1 packed fp16x2: [FIN/2 kpairs][FHID]
__device__ uint32_t g_W1p[(size_t)(FIN / 2) * FHID];

// ---------------- helpers ----------------
__device__ __forceinline__ void mma_fp16(float* d, const uint32_t* a, const uint32_t* b) {
    asm volatile(
      "mma.sync.aligned.m16n8k16.row.col.f32.f16.f16.f32 "
      "{%0,%1,%2,%3}, {%4,%5,%6,%7}, {%8,%9}, {%0,%1,%2,%3};\n"
      : "+f"(d[0]), "+f"(d[1]), "+f"(d[2]), "+f"(d[3])
      : "r"(a[0]), "r"(a[1]), "r"(a[2]), "r"(a[3]), "r"(b[0]), "r"(b[1]));
}

__device__ __forceinline__ uint32_t pack_h2(float x, float y) {
    __half2 t = __floats2half2_rn(x, y);
    return *reinterpret_cast<uint32_t*>(&t);
}

// ---------------- edge index width detection (parallel) -----------------
__global__ void detect_kernel(const void* rowp) {
    const int* p = (const int*)rowp;
    int t = threadIdx.x;                       // 128 threads
    int nz = (p[2 * t + 1] != 0) ? 1 : 0;      // any nonzero high word -> int32 data
    unsigned any = __ballot_sync(0xFFFFFFFFu, nz);
    __shared__ int sh[4];
    if ((t & 31) == 0) sh[t >> 5] = (any != 0);
    __syncthreads();
    if (t == 0)
        g_is64 = !(sh[0] | sh[1] | sh[2] | sh[3]);
}

__device__ __forceinline__ int load_idx(const void* p, int i, int is64) {
    return is64 ? (int)((const long long*)p)[i] : ((const int*)p)[i];
}

// ---------------- W1 fp16 packed pre-convert ----------------------------
__global__ __launch_bounds__(256) void w1cvt_kernel(const float* __restrict__ W1) {
    int i = blockIdx.x * 256 + threadIdx.x;
    if (i >= (FIN / 2) * FHID) return;
    int kp = i / FHID, n = i % FHID;
    float v0 = W1[(size_t)(2 * kp) * FHID + n];
    float v1 = W1[(size_t)(2 * kp + 1) * FHID + n];
    g_W1p[i] = pack_h2(v0, v1);
}

// ---------------- CSR build ----------------
__global__ void zero_deg_kernel() {
    int i = blockIdx.x * 1024 + threadIdx.x;
    if (i < NNODES) g_deg[i] = 0;
}

__global__ __launch_bounds__(256) void hist_kernel(const void* rowp) {
    int i = blockIdx.x * 256 + threadIdx.x;
    if (i >= NEDGES) return;
    int r = load_idx(rowp, i, g_is64);
    atomicAdd(&g_deg[r], 1);
}

__global__ __launch_bounds__(1024) void scan_k1_kernel() {
    __shared__ int sh[1024];
    int t = threadIdx.x;
    int i = blockIdx.x * 1024 + t;
    sh[t] = (i < NNODES) ? g_deg[i] : 0;
    __syncthreads();
    for (int off = 512; off > 0; off >>= 1) {
        if (t < off) sh[t] += sh[t + off];
        __syncthreads();
    }
    if (t == 0) g_bsum[blockIdx.x] = sh[0];
}

__global__ void scan_k2_kernel(int nblocks) {
    __shared__ int sh[128];
    int t = threadIdx.x;
    int x = (t < nblocks) ? g_bsum[t] : 0;
    sh[t] = x;
    __syncthreads();
    for (int off = 1; off < 128; off <<= 1) {
        int v = (t >= off) ? sh[t - off] : 0;
        __syncthreads();
        sh[t] += v;
        __syncthreads();
    }
    if (t < nblocks) g_boff[t] = sh[t] - x;
    if (t == 0) g_rowptr[NNODES] = NEDGES;
}

__global__ __launch_bounds__(1024) void scan_k3_kernel() {
    __shared__ int sh[1024];
    int t = threadIdx.x;
    int i = blockIdx.x * 1024 + t;
    int x = (i < NNODES) ? g_deg[i] : 0;
    sh[t] = x;
    __syncthreads();
    for (int off = 1; off < 1024; off <<= 1) {
        int v = (t >= off) ? sh[t - off] : 0;
        __syncthreads();
        sh[t] += v;
        __syncthreads();
    }
    if (i < NNODES) {
        int excl = sh[t] - x + g_boff[blockIdx.x];
        g_rowptr[i] = excl;
        g_fill[i]   = excl;
    }
}

__global__ __launch_bounds__(256) void scatter_kernel(const void* rowp, const void* colp,
                                                      const float* __restrict__ val) {
    int i = blockIdx.x * 256 + threadIdx.x;
    if (i >= NEDGES) return;
    int is64 = g_is64;
    int r = load_idx(rowp, i, is64);
    int c = load_idx(colp, i, is64);
    int pos = atomicAdd(&g_fill[r], 1);
    g_edge[pos] = make_uint2((uint32_t)c, __float_as_uint(val[i]));
}

// ---------------- GEMM1 (fp16 m16n8k16, reg double-buffer) --------------
// 256 threads, 8 warps (4m x 2n), 128x128 block, BK=16. (Proven R14 form.)
#define AST 12
#define BSTRIDE 136

__global__ __launch_bounds__(256) void gemm1_fp16_kernel(const float* __restrict__ A) {
    __shared__ uint32_t Ash[2][128 * AST];
    __shared__ uint32_t Bsh[2][8 * BSTRIDE];

    const int tid  = threadIdx.x;
    const int lane = tid & 31;
    const int wid  = tid >> 5;
    const int wm   = wid & 3;
    const int wn   = wid >> 2;
    const int bm   = blockIdx.y * 128;
    const int bn   = blockIdx.x * 128;

    const int g  = lane >> 2;
    const int tg = lane & 3;

    float acc[2][8][4];
    #pragma unroll
    for (int i = 0; i < 2; i++)
        #pragma unroll
        for (int j = 0; j < 8; j++)
            #pragma unroll
            for (int q = 0; q < 4; q++) acc[i][j][q] = 0.f;

    float4 aReg[2];
    uint4  bReg;

    const int ldKp = tid >> 5;
    const int ldN4 = (tid & 31) * 4;

    auto store_a = [&](int s, int row, int c4, float4 v) {
        *(uint2*)&Ash[s][row * AST + c4 * 2] =
            make_uint2(pack_h2(v.x, v.y), pack_h2(v.z, v.w));
    };

    #pragma unroll
    for (int i = 0; i < 2; i++) {
        int f = tid + i * 256;
        int row = f >> 2, c4 = f & 3;
        float4 v = make_float4(0.f, 0.f, 0.f, 0.f);
        if (bm + row < NNODES)
            v = *(const float4*)(A + (size_t)(bm + row) * FIN + c4 * 4);
        store_a(0, row, c4, v);
    }
    {
        const size_t gi = (size_t)ldKp * FHID + bn + ldN4;
        *(uint4*)(&Bsh[0][ldKp * BSTRIDE + ldN4]) = *(const uint4*)(g_W1p + gi);
    }
    __syncthreads();

    const int NITER = FIN / 16;
    for (int it = 0; it < NITER; it++) {
        int s = it & 1;
        const uint32_t* aS = Ash[s];
        const uint32_t* bS = Bsh[s];

        if (it + 1 < NITER) {
            int k0 = (it + 1) * 16;
            #pragma unroll
            for (int i = 0; i < 2; i++) {
                int f = tid + i * 256;
                int row = f >> 2, c4 = f & 3;
                aReg[i] = make_float4(0.f, 0.f, 0.f, 0.f);
                if (bm + row < NNODES)
                    aReg[i] = *(const float4*)(A + (size_t)(bm + row) * FIN + k0 + c4 * 4);
            }
            const size_t gi = (size_t)((it + 1) * 8 + ldKp) * FHID + bn + ldN4;
            bReg = *(const uint4*)(g_W1p + gi);
        }

        // A fragments: pure LDS.32, conflict-free (12g+tg covers 32 banks)
        uint32_t a[2][4];
        #pragma unroll
        for (int mt = 0; mt < 2; mt++) {
            int r0 = wm * 32 + mt * 16 + g;
            a[mt][0] = aS[r0 * AST + tg];
            a[mt][1] = aS[(r0 + 8) * AST + tg];
            a[mt][2] = aS[r0 * AST + tg + 4];
            a[mt][3] = aS[(r0 + 8) * AST + tg + 4];
        }

        #pragma unroll
        for (int nt = 0; nt < 8; nt++) {
            int n = wn * 64 + nt * 8 + g;
            uint32_t b[2];
            b[0] = bS[tg * BSTRIDE + n];
            b[1] = bS[(tg + 4) * BSTRIDE + n];
            mma_fp16(acc[0][nt], a[0], b);
            mma_fp16(acc[1][nt], a[1], b);
        }

        if (it + 1 < NITER) {
            int ns = (it + 1) & 1;
            #pragma unroll
            for (int i = 0; i < 2; i++) {
                int f = tid + i * 256;
                int row = f >> 2, c4 = f & 3;
                store_a(ns, row, c4, aReg[i]);
            }
            *(uint4*)(&Bsh[ns][ldKp * BSTRIDE + ldN4]) = bReg;
            __syncthreads();
        }
    }

    // epilogue: write fp16
    #pragma unroll
    for (int mt = 0; mt < 2; mt++) {
        int r0 = bm + wm * 32 + mt * 16 + g;
        #pragma unroll
        for (int nt = 0; nt < 8; nt++) {
            int cc = bn + wn * 64 + nt * 8 + 2 * tg;
            if (r0 < NNODES)
                *(__half2*)(g_H0h + (size_t)r0 * FHID + cc) =
                    __floats2half2_rn(acc[mt][nt][0], acc[mt][nt][1]);
            if (r0 + 8 < NNODES)
                *(__half2*)(g_H0h + (size_t)(r0 + 8) * FHID + cc) =
                    __floats2half2_rn(acc[mt][nt][2], acc[mt][nt][3]);
        }
    }
}

// ---------------- SpMM1 (CSR, warp/row, 8-edge batched fp16 gather) -----
__global__ __launch_bounds__(256) void spmm1_csr_kernel(const float* __restrict__ b1) {
    int row  = blockIdx.x * 8 + (threadIdx.x >> 5);
    int lane = threadIdx.x & 31;
    int start = g_rowptr[row];
    int end   = g_rowptr[row + 1];

    float4 a0 = make_float4(0.f, 0.f, 0.f, 0.f);
    float4 a1 = make_float4(0.f, 0.f, 0.f, 0.f);

    for (int e0 = start; e0 < end; e0 += 32) {
        int m = min(32, end - e0);
        // inactive lanes hold (col=0, val=0): shfl'd contributions are exact zeros
        uint2 ev = make_uint2(0u, 0u);
        if (lane < m) ev = g_edge[e0 + lane];
        for (int j = 0; j < m; j += 8) {
            uint2 q0[8], q1[8];
            float vv[8];
            #pragma unroll
            for (int k = 0; k < 8; k++) {
                int   cj = __shfl_sync(0xFFFFFFFFu, (int)ev.x, j + k);
                vv[k] = __uint_as_float(__shfl_sync(0xFFFFFFFFu, ev.y, j + k));
                const uint2* s = (const uint2*)(g_H0h + (size_t)cj * FHID);
                q0[k] = s[lane];
                q1[k] = s[lane + 32];
            }
            #pragma unroll
            for (int k = 0; k < 8; k++) {
                float2 f0 = __half22float2(*(__half2*)&q0[k].x);
                float2 f1 = __half22float2(*(__half2*)&q0[k].y);
                float2 f2 = __half22float2(*(__half2*)&q1[k].x);
                float2 f3 = __half22float2(*(__half2*)&q1[k].y);
                a0.x = fmaf(vv[k], f0.x, a0.x); a0.y = fmaf(vv[k], f0.y, a0.y);
                a0.z = fmaf(vv[k], f1.x, a0.z); a0.w = fmaf(vv[k], f1.y, a0.w);
                a1.x = fmaf(vv[k], f2.x, a1.x); a1.y = fmaf(vv[k], f2.y, a1.y);
                a1.z = fmaf(vv[k], f3.x, a1.z); a1.w = fmaf(vv[k], f3.y, a1.w);
            }
        }
    }

    const float4* bb = (const float4*)b1;
    float4 t0 = bb[lane], t1 = bb[lane + 32];
    a0.x = fmaxf(a0.x + t0.x, 0.f); a0.y = fmaxf(a0.y + t0.y, 0.f);
    a0.z = fmaxf(a0.z + t0.z, 0.f); a0.w = fmaxf(a0.w + t0.w, 0.f);
    a1.x = fmaxf(a1.x + t1.x, 0.f); a1.y = fmaxf(a1.y + t1.y, 0.f);
    a1.z = fmaxf(a1.z + t1.z, 0.f); a1.w = fmaxf(a1.w + t1.w, 0.f);

    uint2* d = (uint2*)(g_Hh + (size_t)row * FHID);
    uint2 o0, o1;
    *(__half2*)&o0.x = __floats2half2_rn(a0.x, a0.y);
    *(__half2*)&o0.y = __floats2half2_rn(a0.z, a0.w);
    *(__half2*)&o1.x = __floats2half2_rn(a1.x, a1.y);
    *(__half2*)&o1.y = __floats2half2_rn(a1.z, a1.w);
    d[lane]      = o0;
    d[lane + 32] = o1;
}

// ---------------- GEMM2: g_Ph = g_Hh @ W2, smem-staged ------------------
#define HTS 260
#define G2_H_SZ   (64 * HTS)
#define G2_W_SZ   (NCLS * HTS)
#define G2_SMEM_BYTES ((G2_H_SZ + G2_W_SZ) * 4)   // 108160

__global__ __launch_bounds__(256) void gemm2_kernel(const float* __restrict__ W2) {
    extern __shared__ float fsm[];
    float* hT   = fsm;
    float* shWT = fsm + G2_H_SZ;

    const int tid = threadIdx.x;
    const int rowbase = blockIdx.x * 64;

    for (int idx = tid; idx < FHID * NCLS; idx += 256) {
        int k = idx / NCLS, c = idx % NCLS;
        shWT[c * HTS + k] = W2[idx];
    }
    #pragma unroll
    for (int i = 0; i < 16; i++) {
        int idx = tid + i * 256;
        int row = idx >> 6, k4 = idx & 63;
        float2 fa = make_float2(0.f, 0.f), fb = make_float2(0.f, 0.f);
        if (rowbase + row < NNODES) {
            uint2 q = *(const uint2*)(g_Hh + (size_t)(rowbase + row) * FHID + k4 * 4);
            fa = __half22float2(*(__half2*)&q.x);
            fb = __half22float2(*(__half2*)&q.y);
        }
        float* p = &hT[row * HTS + k4 * 4];
        p[0] = fa.x; p[1] = fa.y; p[2] = fb.x; p[3] = fb.y;
    }
    __syncthreads();

    const int rp = tid >> 3;
    const int c0 = (tid & 7) * 5;
    const int lr0 = rp * 2, lr1 = lr0 + 1;

    float acc0[5] = {0.f, 0.f, 0.f, 0.f, 0.f};
    float acc1[5] = {0.f, 0.f, 0.f, 0.f, 0.f};

    #pragma unroll 4
    for (int kq = 0; kq < FHID / 4; kq++) {
        float4 ha = *(const float4*)&hT[lr0 * HTS + kq * 4];
        float4 hb = *(const float4*)&hT[lr1 * HTS + kq * 4];
        #pragma unroll
        for (int j = 0; j < 5; j++) {
            float4 w = *(const float4*)&shWT[(c0 + j) * HTS + kq * 4];
            acc0[j] = fmaf(ha.x, w.x, acc0[j]); acc0[j] = fmaf(ha.y, w.y, acc0[j]);
            acc0[j] = fmaf(ha.z, w.z, acc0[j]); acc0[j] = fmaf(ha.w, w.w, acc0[j]);
            acc1[j] = fmaf(hb.x, w.x, acc1[j]); acc1[j] = fmaf(hb.y, w.y, acc1[j]);
            acc1[j] = fmaf(hb.z, w.z, acc1[j]); acc1[j] = fmaf(hb.w, w.w, acc1[j]);
        }
    }

    int r0 = rowbase + lr0, r1 = rowbase + lr1;
    if (r0 < NNODES) {
        __half* p = g_Ph + (size_t)r0 * NCLS + c0;
        #pragma unroll
        for (int j = 0; j < 5; j++) p[j] = __float2half_rn(acc0[j]);
    }
    if (r1 < NNODES) {
        __half* p = g_Ph + (size_t)r1 * NCLS + c0;
        #pragma unroll
        for (int j = 0; j < 5; j++) p[j] = __float2half_rn(acc1[j]);
    }
}

// ---------------- SpMM2 (CSR, warp/row, 8-edge batched gather) ----------
__global__ __launch_bounds__(256) void spmm2_csr_kernel(const float* __restrict__ b2,
                                                        float* __restrict__ out) {
    int row  = blockIdx.x * 8 + (threadIdx.x >> 5);
    int lane = threadIdx.x & 31;
    int start = g_rowptr[row];
    int end   = g_rowptr[row + 1];

    float ax = 0.f, ay = 0.f;
    const bool act = lane < 20;

    for (int e0 = start; e0 < end; e0 += 32) {
        int m = min(32, end - e0);
        uint2 ev = make_uint2(0u, 0u);
        if (lane < m) ev = g_edge[e0 + lane];
        for (int j = 0; j < m; j += 8) {
            uint32_t pv[8];
            float    vv[8];
            #pragma unroll
            for (int k = 0; k < 8; k++) {
                int   cj = __shfl_sync(0xFFFFFFFFu, (int)ev.x, j + k);
                vv[k] = __uint_as_float(__shfl_sync(0xFFFFFFFFu, ev.y, j + k));
                pv[k] = act ? *(const uint32_t*)((const __half2*)(g_Ph + (size_t)cj * NCLS) + lane)
                            : 0u;
            }
            #pragma unroll
            for (int k = 0; k < 8; k++) {
                float2 f = __half22float2(*(__half2*)&pv[k]);
                ax = fmaf(vv[k], f.x, ax);
                ay = fmaf(vv[k], f.y, ay);
            }
        }
    }

    float v0 = act ? (ax + b2[2 * lane])     : -INFINITY;
    float v1 = act ? (ay + b2[2 * lane + 1]) : -INFINITY;

    float mx = fmaxf(v0, v1);
    #pragma unroll
    for (int off = 16; off > 0; off >>= 1)
        mx = fmaxf(mx, __shfl_xor_sync(0xFFFFFFFFu, mx, off));

    float s = act ? (expf(v0 - mx) + expf(v1 - mx)) : 0.f;
    #pragma unroll
    for (int off = 16; off > 0; off >>= 1)
        s += __shfl_xor_sync(0xFFFFFFFFu, s, off);

    float ls = mx + logf(s);
    if (act)
        *(float2*)(out + (size_t)row * NCLS + 2 * lane) =
            make_float2(v0 - ls, v1 - ls);
}

// ---------------- side-stream resources (created once, OUTSIDE capture) --
struct SideRes {
    cudaStream_t s;
    cudaEvent_t  fork;
    cudaEvent_t  join;
};

static SideRes& side_res() {
    static SideRes r = [] {
        SideRes t;
        cudaStreamCreateWithFlags(&t.s, cudaStreamNonBlocking);
        cudaEventCreateWithFlags(&t.fork, cudaEventDisableTiming);
        cudaEventCreateWithFlags(&t.join, cudaEventDisableTiming);
        return t;
    }();
    return r;
}

// ---------------- launch ----------------
extern "C" void kernel_launch(void* const* d_in, const int* in_sizes, int n_in,
                              void* d_out, int out_size) {
    const float* x    = (const float*)d_in[0];
    const void*  erow = d_in[1];
    const void*  ecol = d_in[2];
    const float* eval = (const float*)d_in[3];
    const float* W1   = (const float*)d_in[4];
    const float* b1   = (const float*)d_in[5];
    const float* W2   = (const float*)d_in[6];
    const float* b2   = (const float*)d_in[7];
    float* out = (float*)d_out;

    const int nchunks = (NNODES + 1023) / 1024;
    SideRes& R = side_res();

    detect_kernel<<<1, 128>>>(erow);

    cudaEventRecord(R.fork, 0);
    cudaStreamWaitEvent(R.s, R.fork, 0);

    zero_deg_kernel<<<nchunks, 1024, 0, R.s>>>();
    hist_kernel<<<NEDGES / 256, 256, 0, R.s>>>(erow);
    scan_k1_kernel<<<nchunks, 1024, 0, R.s>>>();
    scan_k2_kernel<<<1, 128, 0, R.s>>>(nchunks);
    scan_k3_kernel<<<nchunks, 1024, 0, R.s>>>();
    scatter_kernel<<<NEDGES / 256, 256, 0, R.s>>>(erow, ecol, eval);
    cudaEventRecord(R.join, R.s);

    w1cvt_kernel<<<((FIN / 2) * FHID + 255) / 256, 256>>>(W1);
    {
        dim3 grid(FHID / 128, (NNODES + 127) / 128);  // (2, 782)
        gemm1_fp16_kernel<<<grid, 256>>>(x);
    }

    cudaStreamWaitEvent(0, R.join, 0);

    spmm1_csr_kernel<<<NNODES / 8, 256>>>(b1);

    cudaFuncSetAttribute(gemm2_kernel,
                         cudaFuncAttributeMaxDynamicSharedMemorySize, G2_SMEM_BYTES);
    gemm2_kernel<<<(NNODES + 63) / 64, 256, G2_SMEM_BYTES>>>(W2);

    spmm2_csr_kernel<<<NNODES / 8, 256>>>(b2, out);
}